// round 14
// baseline (speedup 1.0000x reference)
#include <cuda_runtime.h>
#include <cuda_fp16.h>
#include <cstdint>

#define KK 32768
#define HH 512
#define BM 128
#define BN 256
#define BD 64
#define KT (HH/BD)   // 8 k-tiles
#define MT (KK/BM)   // 256 M-tiles
#define NSTAGE 3
#define NGATEB 24    // gates-GEMV blocks prepended to k_main grid (512 thr each)

// Static device scratch (no allocations allowed)
__device__ __align__(16) __half g_Wt[HH*HH];     // alpha_weight_hh transposed: [n][d]
__device__ float g_awip[8][HH];                  // awi partials per 64-d chunk
__device__ float g_gatp[8][3*HH];                // gates partials per 64-d chunk
__device__ float g_S1p[HH][MT];                  // per-M-tile partials, [h][mt]
__device__ float g_S2p[HH][MT];

// -------- PTX helpers --------
__device__ __forceinline__ void ldsm4(uint32_t& r0, uint32_t& r1, uint32_t& r2, uint32_t& r3,
                                      uint32_t saddr) {
    asm volatile("ldmatrix.sync.aligned.m8n8.x4.shared.b16 {%0,%1,%2,%3}, [%4];\n"
                 : "=r"(r0), "=r"(r1), "=r"(r2), "=r"(r3) : "r"(saddr));
}
__device__ __forceinline__ void cp16(uint32_t dst, const void* src) {
    asm volatile("cp.async.cg.shared.global [%0], [%1], 16;\n" :: "r"(dst), "l"(src));
}
__device__ __forceinline__ float tanh_fast(float x) {
    float r;
    asm("tanh.approx.f32 %0, %1;" : "=f"(r) : "f"(x));
    return r;
}
// e = exp(sigmoid(x)) with 2 MUFU: tanh.approx + ex2
__device__ __forceinline__ float exp_sigmoid(float x) {
    return __expf(fmaf(0.5f, tanh_fast(0.5f * x), 0.5f));
}
#define CP_COMMIT() asm volatile("cp.async.commit_group;\n" ::: "memory")
#define CP_WAIT(n)  asm volatile("cp.async.wait_group %0;\n" :: "n"(n) : "memory")
#define SWZ(off) ((off) ^ (((off) >> 3) & 0x70))

__device__ __forceinline__ void sts128(uint32_t addr, uint32_t x, uint32_t y,
                                       uint32_t z, uint32_t w) {
    asm volatile("st.shared.v4.b32 [%0], {%1,%2,%3,%4};\n"
                 :: "r"(addr), "r"(x), "r"(y), "r"(z), "r"(w) : "memory");
}
__device__ __forceinline__ uint32_t h2u(__half2 h) { return *(uint32_t*)&h; }

// SMEM layout (dynamic)
#define OFF_SAWI 0
#define OFF_S1   1024
#define OFF_S2   2048
#define OFF_T0   4096
#define ASZ      (BM*BD*2)          // 16384
#define BSZ      (BN*BD*2)          // 32768
#define STG      (ASZ+BSZ)          // 49152
#define SMEM_TOTAL (OFF_T0 + NSTAGE*STG)   // 151552

// ---------------------------------------------------------------- k_prep: transpose + awi partials
__global__ void k_prep(const float* __restrict__ Walpha,
                       const float* __restrict__ inp,
                       const float* __restrict__ aWih) {
    int b = blockIdx.x;
    int tid = threadIdx.x;
    if (b < 256) {                  // ---- transpose alpha_W_hh -> fp16 [n][d]
        __shared__ float tile[32][33];
        int n0 = (b & 15) * 32, d0 = (b >> 4) * 32;
        int tx = tid & 31, ty = tid >> 5;   // 32 x 8
        #pragma unroll
        for (int i = 0; i < 32; i += 8)
            tile[ty + i][tx] = __ldg(&Walpha[(d0 + ty + i) * HH + n0 + tx]);
        __syncthreads();
        #pragma unroll
        for (int i = 0; i < 32; i += 8)
            g_Wt[(n0 + ty + i) * HH + d0 + tx] = __float2half_rn(tile[tx][ty + i]);
    } else {                        // ---- awi partials (coalesced, d-chunked)
        int bb = b - 256;
        int jc = bb & 1, dc = bb >> 1;
        int j = jc * 256 + tid;
        int d0 = dc * 64;
        float s = 0.f;
        #pragma unroll 8
        for (int d = d0; d < d0 + 64; d++)
            s += __ldg(&inp[d]) * __ldg(&aWih[(unsigned)d * HH + j]);
        g_awip[dc][j] = s;
    }
}

// ---------------------------------------------------------------- dummy (shifts ncu capture window onto k_main)
__global__ void k_dummy() {}

// ---------------------------------------------------------------- k_main: [0,24) gates GEMV; [24,536) fused GEMM
__global__ void __launch_bounds__(512, 1) k_main(const float* __restrict__ cinp,
                                                 const float* __restrict__ inp,
                                                 const float* __restrict__ h0,
                                                 const float* __restrict__ Wih,
                                                 const float* __restrict__ Whh) {
    const int tid = threadIdx.x;

    if (blockIdx.x < NGATEB) {      // ---- gates partials, hidden inside GEMM schedule
        int bb = blockIdx.x;
        int jc = bb % 3, dc = bb / 3;
        int j = jc * 512 + tid;
        int d0 = dc * 64;
        float s = 0.f;
        #pragma unroll 8
        for (int d = d0; d < d0 + 64; d++)
            s += __ldg(&h0[d]) * __ldg(&Whh[(unsigned)d * 3 * HH + j])
               + __ldg(&inp[d]) * __ldg(&Wih[(unsigned)d * 3 * HH + j]);
        g_gatp[dc][j] = s;
        return;
    }

    extern __shared__ char smem[];
    const uint32_t sb = (uint32_t)__cvta_generic_to_shared(smem);
    const int b = blockIdx.x - NGATEB;
    const int nt = b >> 8;              // nt-major: wave shares one B panel in L2
    const int mt = b & 255;
    const int n0 = nt * BN, k0 = mt * BM;
    const int lane = tid & 31, w = tid >> 5;       // 16 warps
    const int g = lane >> 2, t = lane & 3;
    const int wm = w >> 2, wn = w & 3;   // 4 (M) x 4 (N) warps, 32x64 tiles

    float* sawi = (float*)(smem + OFF_SAWI);
    float* sS1  = (float*)(smem + OFF_S1);
    float* sS2  = (float*)(smem + OFF_S2);
    if (tid < BN) {
        float aw = 0.f;
        #pragma unroll
        for (int dc = 0; dc < 8; dc++) aw += g_awip[dc][n0 + tid];
        sawi[tid] = aw;
        sS1[tid] = 0.f; sS2[tid] = 0.f;
    }

    uint32_t acc[2][8][2];               // f16x2 accumulators
    #pragma unroll
    for (int a = 0; a < 2; a++)
        #pragma unroll
        for (int bq = 0; bq < 8; bq++) { acc[a][bq][0] = 0u; acc[a][bq][1] = 0u; }

    // A staging registers: tile held one iteration ahead (fp32, 4 float4/thread)
    float4 areg[4];
    const int ar = tid >> 2, acq = tid & 3;        // 128 rows x 4 threads, 16 cols each

    #define LOADA_G(tt) do {                                                        \
        const float4* p = (const float4*)&cinp[(unsigned)(k0 + ar) * HH              \
                                               + (tt) * BD + acq * 16];               \
        areg[0] = __ldg(p);     areg[1] = __ldg(p + 1);                              \
        areg[2] = __ldg(p + 2); areg[3] = __ldg(p + 3);                              \
    } while (0)

    #define STOREA(st) do {                                                         \
        uint32_t abase = sb + OFF_T0 + (st) * STG;                                   \
        uint32_t off0 = (uint32_t)(ar * 128 + acq * 32);                             \
        sts128(abase + SWZ(off0),                                                    \
               h2u(__floats2half2_rn(areg[0].x, areg[0].y)),                         \
               h2u(__floats2half2_rn(areg[0].z, areg[0].w)),                         \
               h2u(__floats2half2_rn(areg[1].x, areg[1].y)),                         \
               h2u(__floats2half2_rn(areg[1].z, areg[1].w)));                        \
        sts128(abase + SWZ(off0 + 16),                                               \
               h2u(__floats2half2_rn(areg[2].x, areg[2].y)),                         \
               h2u(__floats2half2_rn(areg[2].z, areg[2].w)),                         \
               h2u(__floats2half2_rn(areg[3].x, areg[3].y)),                         \
               h2u(__floats2half2_rn(areg[3].z, areg[3].w)));                        \
    } while (0)

    #define LOADB(tt, st) do {                                                      \
        uint32_t bbase = sb + OFF_T0 + (st) * STG + ASZ;                             \
        _Pragma("unroll")                                                            \
        for (int i = 0; i < 4; i++) {                                                \
            int s = tid + i * 512; int r = s >> 3, sc = s & 7;                       \
            uint32_t off = (uint32_t)(r * 128 + sc * 16);                            \
            cp16(bbase + SWZ(off), &g_Wt[(unsigned)(n0 + r) * HH + (tt) * BD + sc * 8]); \
        }                                                                            \
    } while (0)

    // prologue
    LOADA_G(0); STOREA(0);
    LOADA_G(1); STOREA(1);
    LOADA_G(2);                 // held in regs, stored during tt=0
    LOADB(0, 0); CP_COMMIT();
    LOADB(1, 1); CP_COMMIT();
    LOADB(2, 2); CP_COMMIT();

    const int arow = (lane & 15), asel = (lane >> 4) << 3;
    const int brow = (lane & 7) + ((lane >> 4) << 3), bsel = lane & 8;

    for (int tt = 0; tt < KT; tt++) {
        CP_WAIT(2);
        __syncthreads();
        uint32_t abase = sb + OFF_T0 + (tt % NSTAGE) * STG;
        uint32_t bbase = abase + ASZ;
        #pragma unroll
        for (int s = 0; s < 4; s++) {        // four k=16 substeps per BD=64
            int kb = s * 16;
            uint32_t a[2][4], bfr[8][2];
            #pragma unroll
            for (int mi = 0; mi < 2; mi++) {
                uint32_t off = (uint32_t)((wm * 32 + mi * 16 + arow) * 128 + (kb + asel) * 2);
                ldsm4(a[mi][0], a[mi][1], a[mi][2], a[mi][3], abase + SWZ(off));
            }
            #pragma unroll
            for (int np = 0; np < 4; np++) {
                uint32_t off = (uint32_t)((wn * 64 + np * 16 + brow) * 128 + (kb + bsel) * 2);
                ldsm4(bfr[np*2][0], bfr[np*2][1], bfr[np*2+1][0], bfr[np*2+1][1], bbase + SWZ(off));
            }
            #pragma unroll
            for (int mi = 0; mi < 2; mi++)
                #pragma unroll
                for (int n = 0; n < 8; n++)
                    asm volatile(
                        "mma.sync.aligned.m16n8k16.row.col.f16.f16.f16.f16 "
                        "{%0,%1}, {%2,%3,%4,%5}, {%6,%7}, {%0,%1};\n"
                        : "+r"(acc[mi][n][0]), "+r"(acc[mi][n][1])
                        : "r"(a[mi][0]), "r"(a[mi][1]), "r"(a[mi][2]), "r"(a[mi][3]),
                          "r"(bfr[n][0]), "r"(bfr[n][1]));
        }
        __syncthreads();
        if (tt + 2 < KT) STOREA((tt + 2) % NSTAGE);
        if (tt + 3 < KT) {
            LOADA_G(tt + 3);
            LOADB(tt + 3, (tt + 3) % NSTAGE);
        }
        CP_COMMIT();
    }

    // Epilogue: e = exp(sigmoid(x + awi[col])); S1 += e; S2 += c_input(fp32) * e
    #pragma unroll
    for (int n = 0; n < 8; n++) {
        float s1a = 0.f, s1b = 0.f, s2a = 0.f, s2b = 0.f;
        int colL = wn * 64 + n * 8 + 2 * t;
        float awiA = sawi[colL], awiB = sawi[colL + 1];
        #pragma unroll
        for (int mi = 0; mi < 2; mi++) {
            int rowBase = k0 + wm * 32 + mi * 16 + g;
            #pragma unroll
            for (int rr = 0; rr < 2; rr++) {
                int row = rowBase + rr * 8;
                float2 v = __half22float2(*(__half2*)&acc[mi][n][rr]);
                float eA = exp_sigmoid(v.x + awiA);
                float eB = exp_sigmoid(v.y + awiB);
                s1a += eA; s1b += eB;
                float2 cf = *(const float2*)&cinp[(unsigned)row * HH + n0 + colL];
                s2a += cf.x * eA;
                s2b += cf.y * eB;
            }
        }
        #pragma unroll
        for (int off = 4; off < 32; off <<= 1) {
            s1a += __shfl_xor_sync(0xffffffffu, s1a, off);
            s1b += __shfl_xor_sync(0xffffffffu, s1b, off);
            s2a += __shfl_xor_sync(0xffffffffu, s2a, off);
            s2b += __shfl_xor_sync(0xffffffffu, s2b, off);
        }
        if (g == 0) {
            atomicAdd(&sS1[colL],     s1a);
            atomicAdd(&sS1[colL + 1], s1b);
            atomicAdd(&sS2[colL],     s2a);
            atomicAdd(&sS2[colL + 1], s2b);
        }
    }
    __syncthreads();
    if (tid < BN) {
        g_S1p[n0 + tid][mt] = sS1[tid];
        g_S2p[n0 + tid][mt] = sS2[tid];
    }
}

// ---------------------------------------------------------------- k_final: reduce partials + gates + combine
__global__ void k_final(const float* __restrict__ bias,
                        float* __restrict__ out, int out_size) {
    int wg = (blockIdx.x * blockDim.x + threadIdx.x) >> 5;  // [0,512)
    int lane = threadIdx.x & 31;
    int h = wg;
    float S1 = 0.f, S2 = 0.f;
    #pragma unroll
    for (int m = lane; m < MT; m += 32) {
        S1 += g_S1p[h][m];
        S2 += g_S2p[h][m];
    }
    #pragma unroll
    for (int off = 16; off > 0; off >>= 1) {
        S1 += __shfl_xor_sync(0xffffffffu, S1, off);
        S2 += __shfl_xor_sync(0xffffffffu, S2, off);
    }
    // gates: lanes 0-7 -> i(h), 8-15 -> o(HH+h), 16-23 -> g(2HH+h)
    float part = 0.f;
    if (lane < 24) {
        int j = h + (lane >> 3) * HH;
        part = g_gatp[lane & 7][j];
        if ((lane & 7) == 0) part += __ldg(&bias[j]);
    }
    #pragma unroll
    for (int off = 4; off > 0; off >>= 1)
        part += __shfl_xor_sync(0xffffffffu, part, off);
    float gi = __shfl_sync(0xffffffffu, part, 0);
    float go = __shfl_sync(0xffffffffu, part, 8);
    float gG = __shfl_sync(0xffffffffu, part, 16);
    if (lane == 0) {
        float ig = 1.f / (1.f + expf(-gi));
        float og = 1.f / (1.f + expf(-go));
        float gg = tanhf(gG);
        float E0 = expf(ig);
        float denom = E0 + S1 + 1e-12f;
        float c1 = (gg * E0 + S2) / denom;
        float h1 = og * tanhf(c1);
        out[h] = h1;
        if (out_size >= 2 * HH) out[HH + h] = c1;
    }
}

// ----------------------------------------------------------------
extern "C" void kernel_launch(void* const* d_in, const int* in_sizes, int n_in,
                              void* d_out, int out_size) {
    (void)in_sizes; (void)n_in;
    const float* input_  = (const float*)d_in[0];
    const float* c_input = (const float*)d_in[1];
    const float* h_0     = (const float*)d_in[2];
    /* d_in[3] = c_0, unused by the non-empty-children branch */
    const float* w_ih    = (const float*)d_in[4];
    const float* w_hh    = (const float*)d_in[5];
    const float* bias    = (const float*)d_in[6];
    const float* aw_ih   = (const float*)d_in[7];
    const float* aw_hh   = (const float*)d_in[8];

    cudaFuncSetAttribute(k_main, cudaFuncAttributeMaxDynamicSharedMemorySize, SMEM_TOTAL);

    k_prep<<<272, 256>>>(aw_hh, input_, aw_ih);
    k_dummy<<<1, 32>>>();            // shift ncu -s5-c1 window so k_main is captured
    k_dummy<<<1, 32>>>();
    k_main<<<NGATEB + (HH / BN) * MT, 512, SMEM_TOTAL>>>(c_input, input_, h_0, w_ih, w_hh);
    k_final<<<64, 256>>>(bias, (float*)d_out, out_size);
}

// round 15
// speedup vs baseline: 1.1503x; 1.1503x over previous
#include <cuda_runtime.h>
#include <cuda_fp16.h>
#include <cstdint>

#define KK 32768
#define HH 512
#define BM 128
#define BN 256
#define BD 64
#define KT (HH/BD)   // 8 k-tiles
#define MT (KK/BM)   // 256 M-tiles
#define NTILES ((HH/BN)*MT)   // 512 GEMM tiles
#define NSTAGE 3
#define NGATEB 48    // gates-GEMV blocks prepended to k_main grid
#define NHEAVY 148   // persistent GEMM blocks (1 per SM)

// Static device scratch (no allocations allowed)
__device__ __align__(16) __half g_Wt[HH*HH];     // alpha_weight_hh transposed: [n][d]
__device__ float g_awip[8][HH];                  // awi partials per 64-d chunk
__device__ float g_gatp[8][3*HH];                // gates partials per 64-d chunk
__device__ float g_S1p[HH][MT];                  // per-M-tile partials, [h][mt]
__device__ float g_S2p[HH][MT];
__device__ int   g_tile;                         // dynamic tile counter (reset by k_final)

// -------- PTX helpers --------
__device__ __forceinline__ void ldsm4(uint32_t& r0, uint32_t& r1, uint32_t& r2, uint32_t& r3,
                                      uint32_t saddr) {
    asm volatile("ldmatrix.sync.aligned.m8n8.x4.shared.b16 {%0,%1,%2,%3}, [%4];\n"
                 : "=r"(r0), "=r"(r1), "=r"(r2), "=r"(r3) : "r"(saddr));
}
__device__ __forceinline__ void cp16(uint32_t dst, const void* src) {
    asm volatile("cp.async.cg.shared.global [%0], [%1], 16;\n" :: "r"(dst), "l"(src));
}
__device__ __forceinline__ float tanh_fast(float x) {
    float r;
    asm("tanh.approx.f32 %0, %1;" : "=f"(r) : "f"(x));
    return r;
}
// e = exp(sigmoid(x)) with 2 MUFU: tanh.approx + ex2
__device__ __forceinline__ float exp_sigmoid(float x) {
    return __expf(fmaf(0.5f, tanh_fast(0.5f * x), 0.5f));
}
#define CP_COMMIT() asm volatile("cp.async.commit_group;\n" ::: "memory")
#define CP_WAIT(n)  asm volatile("cp.async.wait_group %0;\n" :: "n"(n) : "memory")
#define SWZ(off) ((off) ^ (((off) >> 3) & 0x70))

__device__ __forceinline__ void sts128(uint32_t addr, uint32_t x, uint32_t y,
                                       uint32_t z, uint32_t w) {
    asm volatile("st.shared.v4.b32 [%0], {%1,%2,%3,%4};\n"
                 :: "r"(addr), "r"(x), "r"(y), "r"(z), "r"(w) : "memory");
}
__device__ __forceinline__ uint32_t h2u(__half2 h) { return *(uint32_t*)&h; }

// SMEM layout (dynamic)
#define OFF_SAWI 0
#define OFF_S1   1024
#define OFF_S2   2048
#define OFF_POS  3072
#define OFF_T0   4096
#define ASZ      (BM*BD*2)          // 16384
#define BSZ      (BN*BD*2)          // 32768
#define STG      (ASZ+BSZ)          // 49152
#define SMEM_TOTAL (OFF_T0 + NSTAGE*STG)   // 151552

// ---------------------------------------------------------------- k_prep: transpose + awi partials
__global__ void k_prep(const float* __restrict__ Walpha,
                       const float* __restrict__ inp,
                       const float* __restrict__ aWih) {
    int b = blockIdx.x;
    int tid = threadIdx.x;
    if (b < 256) {                  // ---- transpose alpha_W_hh -> fp16 [n][d]
        __shared__ float tile[32][33];
        int n0 = (b & 15) * 32, d0 = (b >> 4) * 32;
        int tx = tid & 31, ty = tid >> 5;   // 32 x 8
        #pragma unroll
        for (int i = 0; i < 32; i += 8)
            tile[ty + i][tx] = __ldg(&Walpha[(d0 + ty + i) * HH + n0 + tx]);
        __syncthreads();
        #pragma unroll
        for (int i = 0; i < 32; i += 8)
            g_Wt[(n0 + ty + i) * HH + d0 + tx] = __float2half_rn(tile[tx][ty + i]);
    } else {                        // ---- awi partials (coalesced, d-chunked)
        int bb = b - 256;
        int jc = bb & 1, dc = bb >> 1;
        int j = jc * 256 + tid;
        int d0 = dc * 64;
        float s = 0.f;
        #pragma unroll 8
        for (int d = d0; d < d0 + 64; d++)
            s += __ldg(&inp[d]) * __ldg(&aWih[(unsigned)d * HH + j]);
        g_awip[dc][j] = s;
    }
}

// ---------------------------------------------------------------- dummy (shifts ncu capture window onto k_main)
__global__ void k_dummy() {}

// ---------------------------------------------------------------- k_main: [0,48) gates GEMV; [48,196) persistent GEMM
__global__ void __launch_bounds__(256, 1) k_main(const float* __restrict__ cinp,
                                                 const float* __restrict__ inp,
                                                 const float* __restrict__ h0,
                                                 const float* __restrict__ Wih,
                                                 const float* __restrict__ Whh) {
    const int tid = threadIdx.x;

    if (blockIdx.x < NGATEB) {      // ---- gates partials, hidden inside GEMM schedule
        int bb = blockIdx.x;
        int jc = bb % 6, dc = bb / 6;
        int j = jc * 256 + tid;
        int d0 = dc * 64;
        float s = 0.f;
        #pragma unroll 8
        for (int d = d0; d < d0 + 64; d++)
            s += __ldg(&h0[d]) * __ldg(&Whh[(unsigned)d * 3 * HH + j])
               + __ldg(&inp[d]) * __ldg(&Wih[(unsigned)d * 3 * HH + j]);
        g_gatp[dc][j] = s;
        return;
    }

    extern __shared__ char smem[];
    const uint32_t sb = (uint32_t)__cvta_generic_to_shared(smem);
    const int lane = tid & 31, w = tid >> 5;
    const int g = lane >> 2, t = lane & 3;
    const int wm = w >> 2, wn = w & 3;   // 2 (M) x 4 (N) warps, 64x64 tiles

    float* sawi = (float*)(smem + OFF_SAWI);
    float* sS1  = (float*)(smem + OFF_S1);
    float* sS2  = (float*)(smem + OFF_S2);
    int*   spos = (int*)(smem + OFF_POS);

    const int ar = tid >> 3, ahg = tid & 7;
    const int arow = (lane & 15), asel = (lane >> 4) << 3;
    const int brow = (lane & 7) + ((lane >> 4) << 3), bsel = lane & 8;

    float4 areg[4][2];

    #define LOADA_G(tt) do {                                                        \
        _Pragma("unroll")                                                           \
        for (int i = 0; i < 4; i++) {                                               \
            const float4* p = (const float4*)&cinp[(unsigned)(k0 + ar + i * 32) * HH \
                                                   + (tt) * BD + ahg * 8];          \
            areg[i][0] = __ldg(p); areg[i][1] = __ldg(p + 1);                       \
        }                                                                            \
    } while (0)

    #define STOREA(st) do {                                                         \
        uint32_t abase = sb + OFF_T0 + (st) * STG;                                  \
        _Pragma("unroll")                                                           \
        for (int i = 0; i < 4; i++) {                                               \
            uint32_t off = (uint32_t)((ar + i * 32) * 128 + ahg * 16);              \
            __half2 h0v = __floats2half2_rn(areg[i][0].x, areg[i][0].y);            \
            __half2 h1v = __floats2half2_rn(areg[i][0].z, areg[i][0].w);            \
            __half2 h2v = __floats2half2_rn(areg[i][1].x, areg[i][1].y);            \
            __half2 h3v = __floats2half2_rn(areg[i][1].z, areg[i][1].w);            \
            sts128(abase + SWZ(off), h2u(h0v), h2u(h1v), h2u(h2v), h2u(h3v));       \
        }                                                                            \
    } while (0)

    #define LOADB(tt, st) do {                                                      \
        uint32_t bbase = sb + OFF_T0 + (st) * STG + ASZ;                             \
        _Pragma("unroll")                                                            \
        for (int i = 0; i < 8; i++) {                                                \
            int s = tid + i * 256; int r = s >> 3, sc = s & 7;                       \
            uint32_t off = (uint32_t)(r * 128 + sc * 16);                            \
            cp16(bbase + SWZ(off), &g_Wt[(unsigned)(n0 + r) * HH + (tt) * BD + sc * 8]); \
        }                                                                            \
    } while (0)

    for (;;) {
        // ---- grab next tile (dynamic balancing; tail = 1 tile not 1 block)
        if (tid == 0) *spos = atomicAdd(&g_tile, 1);
        __syncthreads();
        int pos = *spos;
        __syncthreads();             // spos free for next round; sS1 reuse guarded below
        if (pos >= NTILES) break;
        const int nt = pos >> 8;     // nt-major: concurrent tiles share one B panel in L2
        const int mt = pos & 255;
        const int n0 = nt * BN, k0 = mt * BM;

        {
            float aw = 0.f;
            #pragma unroll
            for (int dc = 0; dc < 8; dc++) aw += g_awip[dc][n0 + tid];
            sawi[tid] = aw;
        }
        sS1[tid] = 0.f; sS2[tid] = 0.f;

        float acc[4][8][4];
        #pragma unroll
        for (int a = 0; a < 4; a++)
            #pragma unroll
            for (int bq = 0; bq < 8; bq++)
                #pragma unroll
                for (int c = 0; c < 4; c++) acc[a][bq][c] = 0.f;

        // prologue
        LOADA_G(0); STOREA(0);
        LOADA_G(1); STOREA(1);
        LOADA_G(2);                 // held in regs, stored during tt=0
        LOADB(0, 0); CP_COMMIT();
        LOADB(1, 1); CP_COMMIT();
        LOADB(2, 2); CP_COMMIT();

        for (int tt = 0; tt < KT; tt++) {
            CP_WAIT(2);
            __syncthreads();
            uint32_t abase = sb + OFF_T0 + (tt % NSTAGE) * STG;
            uint32_t bbase = abase + ASZ;
            #pragma unroll
            for (int s = 0; s < 4; s++) {        // four k=16 substeps per BD=64
                int kb = s * 16;
                uint32_t a[4][4], bfr[8][2];
                #pragma unroll
                for (int mi = 0; mi < 4; mi++) {
                    uint32_t off = (uint32_t)((wm * 64 + mi * 16 + arow) * 128 + (kb + asel) * 2);
                    ldsm4(a[mi][0], a[mi][1], a[mi][2], a[mi][3], abase + SWZ(off));
                }
                #pragma unroll
                for (int np = 0; np < 4; np++) {
                    uint32_t off = (uint32_t)((wn * 64 + np * 16 + brow) * 128 + (kb + bsel) * 2);
                    ldsm4(bfr[np*2][0], bfr[np*2][1], bfr[np*2+1][0], bfr[np*2+1][1],
                          bbase + SWZ(off));
                }
                #pragma unroll
                for (int mi = 0; mi < 4; mi++)
                    #pragma unroll
                    for (int n = 0; n < 8; n++)
                        asm volatile(
                            "mma.sync.aligned.m16n8k16.row.col.f32.f16.f16.f32 "
                            "{%0,%1,%2,%3}, {%4,%5,%6,%7}, {%8,%9}, {%0,%1,%2,%3};\n"
                            : "+f"(acc[mi][n][0]), "+f"(acc[mi][n][1]),
                              "+f"(acc[mi][n][2]), "+f"(acc[mi][n][3])
                            : "r"(a[mi][0]), "r"(a[mi][1]), "r"(a[mi][2]), "r"(a[mi][3]),
                              "r"(bfr[n][0]), "r"(bfr[n][1]));
            }
            __syncthreads();
            if (tt + 2 < KT) STOREA((tt + 2) % NSTAGE);
            if (tt + 3 < KT) {
                LOADA_G(tt + 3);
                LOADB(tt + 3, (tt + 3) % NSTAGE);
            }
            CP_COMMIT();
        }

        // Epilogue: e = exp(sigmoid(x + awi[col])); S1 += e; S2 += c_input(fp32) * e
        #pragma unroll
        for (int n = 0; n < 8; n++) {
            float s1a = 0.f, s1b = 0.f, s2a = 0.f, s2b = 0.f;
            int colL = wn * 64 + n * 8 + 2 * t;
            float awiA = sawi[colL], awiB = sawi[colL + 1];
            #pragma unroll
            for (int mi = 0; mi < 4; mi++) {
                int rowBase = k0 + wm * 64 + mi * 16 + g;
                #pragma unroll
                for (int rr = 0; rr < 2; rr++) {
                    int row = rowBase + rr * 8;
                    float eA = exp_sigmoid(acc[mi][n][rr * 2 + 0] + awiA);
                    float eB = exp_sigmoid(acc[mi][n][rr * 2 + 1] + awiB);
                    s1a += eA; s1b += eB;
                    float2 cf = *(const float2*)&cinp[(unsigned)row * HH + n0 + colL];
                    s2a += cf.x * eA;
                    s2b += cf.y * eB;
                }
            }
            #pragma unroll
            for (int off = 4; off < 32; off <<= 1) {
                s1a += __shfl_xor_sync(0xffffffffu, s1a, off);
                s1b += __shfl_xor_sync(0xffffffffu, s1b, off);
                s2a += __shfl_xor_sync(0xffffffffu, s2a, off);
                s2b += __shfl_xor_sync(0xffffffffu, s2b, off);
            }
            if (g == 0) {
                atomicAdd(&sS1[colL],     s1a);
                atomicAdd(&sS1[colL + 1], s1b);
                atomicAdd(&sS2[colL],     s2a);
                atomicAdd(&sS2[colL + 1], s2b);
            }
        }
        __syncthreads();
        g_S1p[n0 + tid][mt] = sS1[tid];
        g_S2p[n0 + tid][mt] = sS2[tid];
        __syncthreads();             // sS1/sS2 stores done before next tile zeroes them
    }
}

// ---------------------------------------------------------------- k_final: reduce partials + gates + combine (+ counter reset)
__global__ void k_final(const float* __restrict__ bias,
                        float* __restrict__ out, int out_size) {
    if (blockIdx.x == 0 && threadIdx.x == 0) g_tile = 0;   // reset for next graph replay
    int wg = (blockIdx.x * blockDim.x + threadIdx.x) >> 5;  // [0,512)
    int lane = threadIdx.x & 31;
    int h = wg;
    float S1 = 0.f, S2 = 0.f;
    #pragma unroll
    for (int m = lane; m < MT; m += 32) {
        S1 += g_S1p[h][m];
        S2 += g_S2p[h][m];
    }
    #pragma unroll
    for (int off = 16; off > 0; off >>= 1) {
        S1 += __shfl_xor_sync(0xffffffffu, S1, off);
        S2 += __shfl_xor_sync(0xffffffffu, S2, off);
    }
    // gates: lanes 0-7 -> i(h), 8-15 -> o(HH+h), 16-23 -> g(2HH+h)
    float part = 0.f;
    if (lane < 24) {
        int j = h + (lane >> 3) * HH;
        part = g_gatp[lane & 7][j];
        if ((lane & 7) == 0) part += __ldg(&bias[j]);
    }
    #pragma unroll
    for (int off = 4; off > 0; off >>= 1)
        part += __shfl_xor_sync(0xffffffffu, part, off);
    float gi = __shfl_sync(0xffffffffu, part, 0);
    float go = __shfl_sync(0xffffffffu, part, 8);
    float gG = __shfl_sync(0xffffffffu, part, 16);
    if (lane == 0) {
        float ig = 1.f / (1.f + expf(-gi));
        float og = 1.f / (1.f + expf(-go));
        float gg = tanhf(gG);
        float E0 = expf(ig);
        float denom = E0 + S1 + 1e-12f;
        float c1 = (gg * E0 + S2) / denom;
        float h1 = og * tanhf(c1);
        out[h] = h1;
        if (out_size >= 2 * HH) out[HH + h] = c1;
    }
}

// ----------------------------------------------------------------
extern "C" void kernel_launch(void* const* d_in, const int* in_sizes, int n_in,
                              void* d_out, int out_size) {
    (void)in_sizes; (void)n_in;
    const float* input_  = (const float*)d_in[0];
    const float* c_input = (const float*)d_in[1];
    const float* h_0     = (const float*)d_in[2];
    /* d_in[3] = c_0, unused by the non-empty-children branch */
    const float* w_ih    = (const float*)d_in[4];
    const float* w_hh    = (const float*)d_in[5];
    const float* bias    = (const float*)d_in[6];
    const float* aw_ih   = (const float*)d_in[7];
    const float* aw_hh   = (const float*)d_in[8];

    cudaFuncSetAttribute(k_main, cudaFuncAttributeMaxDynamicSharedMemorySize, SMEM_TOTAL);

    k_prep<<<272, 256>>>(aw_hh, input_, aw_ih);
    k_dummy<<<1, 32>>>();            // shift ncu -s5-c1 window so k_main is captured
    k_dummy<<<1, 32>>>();
    k_main<<<NGATEB + NHEAVY, 256, SMEM_TOTAL>>>(c_input, input_, h_0, w_ih, w_hh);
    k_final<<<64, 256>>>(bias, (float*)d_out, out_size);
}